// round 1
// baseline (speedup 1.0000x reference)
#include <cuda_runtime.h>
#include <cuda_fp16.h>
#include <cstdint>

#define TT 256
#define BB 128
#define EE 512
#define HH 1024
#define G4 4096

// ---------------- scratch (static device allocations; no cudaMalloc) ----------------
__device__ __half g_emb[(size_t)TT * BB * EE];          // gathered embeddings, fp16, (T*B, E)
__device__ __half g_wxp[2][(size_t)G4 * EE];            // Wx^T permuted fp16: [n'][k], n'=4j+g
__device__ __half g_whp[2][(size_t)G4 * HH];            // Wh^T permuted fp16: [n'][k]
__device__ float  g_xp[2][(size_t)TT * BB * G4];        // x-projection + bias, fp32, rows t*B+b
__device__ __half g_Hst[2][2][BB * HH];                 // [parity][dir] hidden state fp16
__device__ float  g_C[2][BB * HH];                      // cell state fp32
__device__ float  g_maxH[2][BB * HH];                   // running max of H (fp32, pre-rounding)
__device__ float  g_h1[BB * 512];                       // classifier hidden

// ---------------- mma.sync m16n8k16 fp16 -> fp32 ----------------
__device__ __forceinline__ void mma16816(float* c,
    uint32_t a0, uint32_t a1, uint32_t a2, uint32_t a3, uint32_t b0, uint32_t b1)
{
    asm volatile(
        "mma.sync.aligned.m16n8k16.row.col.f32.f16.f16.f32 "
        "{%0,%1,%2,%3},{%4,%5,%6,%7},{%8,%9},{%0,%1,%2,%3};\n"
        : "+f"(c[0]), "+f"(c[1]), "+f"(c[2]), "+f"(c[3])
        : "r"(a0), "r"(a1), "r"(a2), "r"(a3), "r"(b0), "r"(b1));
}

// Generic tile GEMM: C(128 x 64) += A(m0.., K) * B^T(n0.., K)
// A row-major M x K (fp16), Bw row-major N x K (fp16, i.e. B col-major).
// smem: As = half[2][128][40], Bs = half[2][64][40] (passed flat).
// acc[2][4][4] per thread. 256 threads, warps arranged 4(m) x 2(n), warp tile 32x32.
__device__ __forceinline__ void gemm_core(
    const __half* __restrict__ A, const __half* __restrict__ Bw,
    int K, int m0, int n0, __half* As, __half* Bs, float acc[2][4][4])
{
    const int tid  = threadIdx.x;
    const int lane = tid & 31, warp = tid >> 5;
    const int wm = (warp & 3) * 32, wn = (warp >> 2) * 32;
    const int g = lane >> 2, tg = lane & 3;
    const int KT = K >> 5;

    auto load_stage = [&](int s, int kt) {
        const int k0 = kt << 5;
#pragma unroll
        for (int i = 0; i < 2; i++) {
            int li = tid + (i << 8);
            int r = li >> 2, kc = (li & 3) << 3;
            *(uint4*)(As + (size_t)s * 5120 + r * 40 + kc) =
                *(const uint4*)(A + (size_t)(m0 + r) * K + k0 + kc);
        }
        {
            int r = tid >> 2, kc = (tid & 3) << 3;
            *(uint4*)(Bs + (size_t)s * 2560 + r * 40 + kc) =
                *(const uint4*)(Bw + (size_t)(n0 + r) * K + k0 + kc);
        }
    };

    load_stage(0, 0);
    __syncthreads();

    for (int kt = 0; kt < KT; kt++) {
        const int s = kt & 1;
        if (kt + 1 < KT) load_stage(s ^ 1, kt + 1);
#pragma unroll
        for (int ks = 0; ks < 32; ks += 16) {
            uint32_t a[2][4];
            uint32_t bfr[4][2];
#pragma unroll
            for (int mi = 0; mi < 2; mi++) {
                const __half* ap = As + (size_t)s * 5120 + (wm + mi * 16 + g) * 40 + ks + 2 * tg;
                a[mi][0] = *(const uint32_t*)ap;
                a[mi][1] = *(const uint32_t*)(ap + 8 * 40);
                a[mi][2] = *(const uint32_t*)(ap + 8);
                a[mi][3] = *(const uint32_t*)(ap + 8 * 40 + 8);
            }
#pragma unroll
            for (int ni = 0; ni < 4; ni++) {
                const __half* bp = Bs + (size_t)s * 2560 + (wn + ni * 8 + g) * 40 + ks + 2 * tg;
                bfr[ni][0] = *(const uint32_t*)bp;
                bfr[ni][1] = *(const uint32_t*)(bp + 8);
            }
#pragma unroll
            for (int mi = 0; mi < 2; mi++)
#pragma unroll
                for (int ni = 0; ni < 4; ni++)
                    mma16816(acc[mi][ni], a[mi][0], a[mi][1], a[mi][2], a[mi][3],
                             bfr[ni][0], bfr[ni][1]);
        }
        __syncthreads();
    }
}

__device__ __forceinline__ float sigf(float x) { return 1.0f / (1.0f + __expf(-x)); }

// ---------------- init ----------------
__global__ void init_kernel()
{
    const int i = blockIdx.x * 256 + threadIdx.x;   // 0 .. BB*HH-1
    const int d = blockIdx.y;
    if (i < BB * HH) {
        g_Hst[0][d][i] = __float2half(0.0f);
        g_C[d][i] = 0.0f;
        g_maxH[d][i] = -3.0e38f;
    }
}

// ---------------- weight prep: transpose + fp16 + gate interleave ----------------
// dst[n'][k] = (half) src[k*4096 + (n'%4)*1024 + n'/4]
__global__ void prep_w(const float* __restrict__ src, int which, int K)
{
    __half* dst = (which == 0) ? g_wxp[0] : (which == 1) ? g_wxp[1]
                : (which == 2) ? g_whp[0] : g_whp[1];
    const int np = blockIdx.x;                       // 0..4095
    const int c = ((np & 3) << 10) | (np >> 2);      // original column
    for (int k = threadIdx.x; k < K; k += 256)
        dst[(size_t)np * K + k] = __float2half(src[(size_t)k * G4 + c]);
}

// ---------------- embedding gather ----------------
__global__ void gather_emb(const int* __restrict__ inputs, const float* __restrict__ table)
{
    const int r = blockIdx.x;                        // t*B + b
    const int t = r >> 7, b = r & 127;
    const int idx = inputs[b * TT + t];
    const float* src = table + (size_t)idx * EE;
    __half* dst = g_emb + (size_t)r * EE;
    const int e = threadIdx.x * 4;                   // 128 threads * 4 = 512
    float4 v = *(const float4*)(src + e);
    dst[e + 0] = __float2half(v.x);
    dst[e + 1] = __float2half(v.y);
    dst[e + 2] = __float2half(v.z);
    dst[e + 3] = __float2half(v.w);
}

// ---------------- projection GEMM: xp = emb @ Wx (permuted) + bias ----------------
__global__ __launch_bounds__(256) void proj_kernel(
    const float* __restrict__ bias_f, const float* __restrict__ bias_b)
{
    __shared__ __half As[2 * 128 * 40];
    __shared__ __half Bs[2 * 64 * 40];

    const int nt = blockIdx.x;       // 0..63
    const int mt = blockIdx.y;       // 0..255
    const int dir = blockIdx.z;
    const int m0 = mt * 128, n0 = nt * 64;
    const float* bias = dir ? bias_b : bias_f;
    float* xp = g_xp[dir];

    float acc[2][4][4];
#pragma unroll
    for (int a = 0; a < 2; a++)
#pragma unroll
        for (int b = 0; b < 4; b++)
#pragma unroll
            for (int c = 0; c < 4; c++) acc[a][b][c] = 0.0f;

    gemm_core(g_emb, g_wxp[dir], EE, m0, n0, As, Bs, acc);

    const int lane = threadIdx.x & 31, warp = threadIdx.x >> 5;
    const int wm = (warp & 3) * 32, wn = (warp >> 2) * 32;
    const int g = lane >> 2, tg = lane & 3;
#pragma unroll
    for (int mi = 0; mi < 2; mi++) {
        const int r0 = m0 + wm + mi * 16 + g;
#pragma unroll
        for (int ni = 0; ni < 4; ni++) {
            const int c0 = n0 + wn + ni * 8 + 2 * tg;
            const float b0v = bias[((c0) & 3) * 1024 + (c0 >> 2)];
            const float b1v = bias[((c0 + 1) & 3) * 1024 + ((c0 + 1) >> 2)];
            float2 v0 = make_float2(acc[mi][ni][0] + b0v, acc[mi][ni][1] + b1v);
            float2 v1 = make_float2(acc[mi][ni][2] + b0v, acc[mi][ni][3] + b1v);
            *(float2*)&xp[(size_t)r0 * G4 + c0] = v0;
            *(float2*)&xp[(size_t)(r0 + 8) * G4 + c0] = v1;
        }
    }
}

// ---------------- one recurrence step (both directions via blockIdx.y) ----------------
struct SmemAB { __half As[2 * 128 * 40]; __half Bs[2 * 64 * 40]; };
union SmemU { SmemAB ab; float gbuf[128 * 68]; };

__global__ __launch_bounds__(256) void step_kernel(int t)
{
    __shared__ SmemU u;

    const int nt = blockIdx.x;       // 0..63 -> hidden units [nt*16, nt*16+16)
    const int dir = blockIdx.y;
    const int par = t & 1;
    const int n0 = nt * 64;

    float acc[2][4][4];
#pragma unroll
    for (int a = 0; a < 2; a++)
#pragma unroll
        for (int b = 0; b < 4; b++)
#pragma unroll
            for (int c = 0; c < 4; c++) acc[a][b][c] = 0.0f;

    gemm_core(g_Hst[par][dir], g_whp[dir], HH, 0, n0, u.ab.As, u.ab.Bs, acc);
    // gemm_core ends with __syncthreads(); safe to overwrite the union.

    const int lane = threadIdx.x & 31, warp = threadIdx.x >> 5;
    const int wm = (warp & 3) * 32, wn = (warp >> 2) * 32;
    const int g = lane >> 2, tg = lane & 3;
#pragma unroll
    for (int mi = 0; mi < 2; mi++) {
        const int r0 = wm + mi * 16 + g;
#pragma unroll
        for (int ni = 0; ni < 4; ni++) {
            const int c0 = wn + ni * 8 + 2 * tg;
            *(float2*)&u.gbuf[r0 * 68 + c0]       = make_float2(acc[mi][ni][0], acc[mi][ni][1]);
            *(float2*)&u.gbuf[(r0 + 8) * 68 + c0] = make_float2(acc[mi][ni][2], acc[mi][ni][3]);
        }
    }
    __syncthreads();

    const int xbase = (dir == 0) ? t : (TT - 1 - t);
    for (int it = threadIdx.x; it < BB * 16; it += 256) {
        const int b = it >> 4, jj = it & 15;
        float4 gv = *(float4*)&u.gbuf[b * 68 + 4 * jj];
        const float* xptr = &g_xp[dir][((size_t)xbase * BB + b) * G4 + n0 + 4 * jj];
        float4 xv = *(const float4*)xptr;
        const float pi = gv.x + xv.x, pf = gv.y + xv.y, po = gv.z + xv.z, pc = gv.w + xv.w;
        float iv, fv, ov;
        if (dir == 0) { iv = sigf(pi); fv = sigf(pf); ov = sigf(po); }
        else          { iv = sigf(sigf(pi)); fv = sigf(sigf(pf)); ov = sigf(sigf(po)); }
        const float cv = tanhf(pc);
        const int idx = b * HH + nt * 16 + jj;
        const float Cn = fv * g_C[dir][idx] + iv * cv;
        g_C[dir][idx] = Cn;
        const float Hn = ov * tanhf(Cn);
        g_Hst[par ^ 1][dir][idx] = __float2half(Hn);
        g_maxH[dir][idx] = fmaxf(g_maxH[dir][idx], Hn);
    }
}

// ---------------- classifier ----------------
__global__ __launch_bounds__(256) void fc1_kernel(const float* __restrict__ W1,
                                                  const float* __restrict__ b1)
{
    __shared__ float p[4][2048];
    const int b0 = blockIdx.x * 4;
    for (int i = threadIdx.x; i < 4 * 2048; i += 256) {
        const int r = i >> 11, c = i & 2047;
        float v = (c < 1024) ? g_maxH[0][(b0 + r) * HH + c]
                             : g_maxH[1][(b0 + r) * HH + (c - 1024)];
        p[r][c] = fmaxf(v, 0.0f);
    }
    __syncthreads();
    for (int j = threadIdx.x; j < 512; j += 256) {
        float a0 = b1[j], a1 = b1[j], a2 = b1[j], a3 = b1[j];
        for (int k = 0; k < 2048; k++) {
            const float w = W1[(size_t)k * 512 + j];
            a0 += p[0][k] * w; a1 += p[1][k] * w;
            a2 += p[2][k] * w; a3 += p[3][k] * w;
        }
        g_h1[(b0 + 0) * 512 + j] = a0;
        g_h1[(b0 + 1) * 512 + j] = a1;
        g_h1[(b0 + 2) * 512 + j] = a2;
        g_h1[(b0 + 3) * 512 + j] = a3;
    }
}

__global__ void fc2_kernel(const float* __restrict__ W2, const float* __restrict__ b2,
                           float* __restrict__ out)
{
    const int o = blockIdx.x * 256 + threadIdx.x;
    if (o < BB * 5) {
        const int b = o / 5, l = o % 5;
        float acc = b2[l];
        for (int k = 0; k < 512; k++)
            acc += g_h1[b * 512 + k] * W2[k * 5 + l];
        out[o] = acc;
    }
}

// ---------------- launch ----------------
extern "C" void kernel_launch(void* const* d_in, const int* in_sizes, int n_in,
                              void* d_out, int out_size)
{
    const int*   inputs    = (const int*)  d_in[0];
    const float* emb_table = (const float*)d_in[1];
    const float* Wxf       = (const float*)d_in[2];
    const float* Whf       = (const float*)d_in[3];
    const float* bhf       = (const float*)d_in[4];
    const float* Wxb       = (const float*)d_in[5];
    const float* Whb       = (const float*)d_in[6];
    const float* bhb       = (const float*)d_in[7];
    const float* W1        = (const float*)d_in[8];
    const float* b1        = (const float*)d_in[9];
    const float* W2        = (const float*)d_in[10];
    const float* b2        = (const float*)d_in[11];
    float* out = (float*)d_out;

    init_kernel<<<dim3(512, 2), 256>>>();
    prep_w<<<G4, 256>>>(Wxf, 0, EE);
    prep_w<<<G4, 256>>>(Wxb, 1, EE);
    prep_w<<<G4, 256>>>(Whf, 2, HH);
    prep_w<<<G4, 256>>>(Whb, 3, HH);
    gather_emb<<<TT * BB, 128>>>(inputs, emb_table);
    proj_kernel<<<dim3(64, 256, 2), 256>>>(bhf, bhb);
    for (int t = 0; t < TT; t++)
        step_kernel<<<dim3(64, 2), 256>>>(t);
    fc1_kernel<<<32, 256>>>(W1, b1);
    fc2_kernel<<<3, 256>>>(W2, b2, out);
}

// round 3
// speedup vs baseline: 1.9131x; 1.9131x over previous
#include <cuda_runtime.h>
#include <cuda_fp16.h>
#include <cstdint>

#define TT 256
#define BB 128
#define EE 512
#define HH 1024
#define G4 4096
#define NCTAS 128
#define CW   128      // K-chunk width
#define ASTR 136      // staged tile row stride (halfs): 272B -> conflict-free LDSM
#define SWH  1032     // resident Wh row stride (halfs): 2064B -> conflict-free LDSM

// ---------------- static device scratch ----------------
__device__ __half g_emb[(size_t)TT * BB * EE];
__device__ __half g_wxp[2][(size_t)G4 * EE];
__device__ __half g_whp[2][(size_t)G4 * HH];
__device__ float  g_xp[2][(size_t)TT * BB * G4];
__device__ __half g_Hst[2][2][BB * HH];
__device__ float  g_maxH[2][BB * HH];
__device__ float  g_h1[BB * 512];
__device__ unsigned g_cnt, g_gen;

// ---------------- primitives ----------------
__device__ __forceinline__ uint32_t cvs(const void* p) {
    return (uint32_t)__cvta_generic_to_shared(p);
}
__device__ __forceinline__ void mma16816(float* c, const uint32_t a[4],
                                         uint32_t b0, uint32_t b1)
{
    asm volatile(
        "mma.sync.aligned.m16n8k16.row.col.f32.f16.f16.f32 "
        "{%0,%1,%2,%3},{%4,%5,%6,%7},{%8,%9},{%0,%1,%2,%3};\n"
        : "+f"(c[0]), "+f"(c[1]), "+f"(c[2]), "+f"(c[3])
        : "r"(a[0]), "r"(a[1]), "r"(a[2]), "r"(a[3]), "r"(b0), "r"(b1));
}
__device__ __forceinline__ void ldsm4(uint32_t& r0, uint32_t& r1, uint32_t& r2,
                                      uint32_t& r3, uint32_t a)
{
    asm volatile("ldmatrix.sync.aligned.m8n8.x4.shared.b16 {%0,%1,%2,%3},[%4];"
                 : "=r"(r0), "=r"(r1), "=r"(r2), "=r"(r3) : "r"(a));
}
__device__ __forceinline__ void cp16(uint32_t d, const void* s) {
    asm volatile("cp.async.cg.shared.global [%0], [%1], 16;" :: "r"(d), "l"(s));
}
__device__ __forceinline__ void cp_commit() {
    asm volatile("cp.async.commit_group;");
}
template <int N> __device__ __forceinline__ void cp_wait() {
    asm volatile("cp.async.wait_group %0;" :: "n"(N));
}
__device__ __forceinline__ float tanh_a(float x) {
    float y; asm("tanh.approx.f32 %0, %1;" : "=f"(y) : "f"(x)); return y;
}
__device__ __forceinline__ float sig_a(float x) {
    return 0.5f * tanh_a(0.5f * x) + 0.5f;
}

__device__ __forceinline__ void grid_sync()
{
    __syncthreads();
    if (threadIdx.x == 0) {
        __threadfence();
        unsigned gen = atomicAdd(&g_gen, 0u);
        if (atomicAdd(&g_cnt, 1u) == NCTAS - 1u) {
            atomicExch(&g_cnt, 0u);
            __threadfence();
            atomicAdd(&g_gen, 1u);
        } else {
            while (atomicAdd(&g_gen, 0u) == gen) { }
        }
        __threadfence();
    }
    __syncthreads();
}

// One K-chunk of the 128x64 tile GEMM. aB: smem byte addr of A stage
// (row stride ASTR). bB: smem byte addr of B chunk base (row stride BSTR).
template <int BSTR>
__device__ __forceinline__ void mma_chunk(uint32_t aB, uint32_t bB,
    float acc[2][4][4], int lane, int wm, int wn)
{
    const int ar  = lane & 15, akh = (lane >> 4) << 3;
    const int br  = lane & 7;
    const int sel = lane >> 3;
    const int bni = (sel >> 1) << 3, bkh = (sel & 1) << 3;
#pragma unroll
    for (int ks = 0; ks < CW; ks += 16) {
        uint32_t a[2][4], b[4][2];
#pragma unroll
        for (int mi = 0; mi < 2; mi++)
            ldsm4(a[mi][0], a[mi][1], a[mi][2], a[mi][3],
                  aB + (uint32_t)(((wm + mi * 16 + ar) * ASTR + ks + akh) << 1));
#pragma unroll
        for (int p = 0; p < 2; p++)
            ldsm4(b[2 * p][0], b[2 * p][1], b[2 * p + 1][0], b[2 * p + 1][1],
                  bB + (uint32_t)(((wn + p * 16 + bni + br) * BSTR + ks + bkh) << 1));
#pragma unroll
        for (int mi = 0; mi < 2; mi++)
#pragma unroll
            for (int ni = 0; ni < 4; ni++)
                mma16816(acc[mi][ni], a[mi], b[ni][0], b[ni][1]);
    }
}

// ---------------- init ----------------
__global__ void init_kernel()
{
    const int i = blockIdx.x * 256 + threadIdx.x;
    const int d = blockIdx.y;
    if (i < BB * HH) g_Hst[0][d][i] = __float2half(0.0f);
    if (blockIdx.x == 0 && blockIdx.y == 0 && threadIdx.x == 0) {
        g_cnt = 0u; g_gen = 0u;
    }
}

// ---------------- weight prep: tiled transpose + fp16 + gate interleave ----------------
__global__ void prep_w2(const float* __restrict__ src, int which, int K)
{
    __half* dst = (which == 0) ? g_wxp[0] : (which == 1) ? g_wxp[1]
                : (which == 2) ? g_whp[0] : g_whp[1];
    __shared__ float tile[32][33];
    const int kt = blockIdx.x * 32;
    const int ct = blockIdx.y * 32;
    const int tx = threadIdx.x & 31, ty = threadIdx.x >> 5;
#pragma unroll
    for (int r = 0; r < 32; r += 8)
        tile[ty + r][tx] = src[(size_t)(kt + ty + r) * G4 + ct + tx];
    __syncthreads();
#pragma unroll
    for (int r = 0; r < 32; r += 8) {
        const int c  = ct + ty + r;
        const int np = ((c & 1023) << 2) | (c >> 10);
        dst[(size_t)np * K + kt + tx] = __float2half(tile[tx][ty + r]);
    }
}

// ---------------- embedding gather ----------------
__global__ void gather_emb(const int* __restrict__ inputs, const float* __restrict__ table)
{
    const int r = blockIdx.x;                 // t*B + b
    const int t = r >> 7, b = r & 127;
    const int idx = inputs[b * TT + t];
    const float* src = table + (size_t)idx * EE;
    __half* dst = g_emb + (size_t)r * EE;
    const int e = threadIdx.x * 4;
    float4 v = *(const float4*)(src + e);
    dst[e + 0] = __float2half(v.x);
    dst[e + 1] = __float2half(v.y);
    dst[e + 2] = __float2half(v.z);
    dst[e + 3] = __float2half(v.w);
}

// ---------------- projection GEMM: xp = emb @ Wx (permuted) + bias ----------------
#define PROJ_SMEM ((2 * 128 * ASTR + 2 * 64 * ASTR) * 2)

__global__ __launch_bounds__(256) void proj_kernel(
    const float* __restrict__ bias_f, const float* __restrict__ bias_b)
{
    extern __shared__ __half psm[];
    __half* As = psm;
    __half* Bs = psm + 2 * 128 * ASTR;

    const int nt = blockIdx.x, mt = blockIdx.y, dir = blockIdx.z;
    const int m0 = mt * 128, n0 = nt * 64;
    const __half* Ag = g_emb + (size_t)m0 * EE;
    const __half* Bg = g_wxp[dir] + (size_t)n0 * EE;
    const float* bias = dir ? bias_b : bias_f;
    float* xp = g_xp[dir];

    const uint32_t asB = cvs(As), bsB = cvs(Bs);
    const int tid = threadIdx.x, lane = tid & 31, warp = tid >> 5;
    const int wm = (warp & 3) * 32, wn = (warp >> 2) * 32;

    auto loadA = [&](int s, int kc) {
#pragma unroll
        for (int i = 0; i < 8; i++) {
            int u = tid + i * 256, r = u >> 4, c8 = (u & 15) * 8;
            cp16(asB + (uint32_t)((s * 128 * ASTR + r * ASTR + c8) << 1),
                 Ag + (size_t)r * EE + kc + c8);
        }
    };
    auto loadB = [&](int s, int kc) {
#pragma unroll
        for (int i = 0; i < 4; i++) {
            int u = tid + i * 256, r = u >> 4, c8 = (u & 15) * 8;
            cp16(bsB + (uint32_t)((s * 64 * ASTR + r * ASTR + c8) << 1),
                 Bg + (size_t)r * EE + kc + c8);
        }
    };

    float acc[2][4][4];
#pragma unroll
    for (int a = 0; a < 2; a++)
#pragma unroll
        for (int b = 0; b < 4; b++)
#pragma unroll
            for (int c = 0; c < 4; c++) acc[a][b][c] = 0.0f;

    loadA(0, 0); loadB(0, 0); cp_commit();
    const int NC = EE / CW;   // 4
#pragma unroll 1
    for (int c = 0; c < NC; c++) {
        if (c + 1 < NC) {
            loadA((c + 1) & 1, (c + 1) * CW);
            loadB((c + 1) & 1, (c + 1) * CW);
            cp_commit();
            cp_wait<1>();
        } else {
            cp_wait<0>();
        }
        __syncthreads();
        mma_chunk<ASTR>(asB + (uint32_t)(((c & 1) * 128 * ASTR) << 1),
                        bsB + (uint32_t)(((c & 1) * 64 * ASTR) << 1),
                        acc, lane, wm, wn);
        __syncthreads();
    }

    const int g = lane >> 2, tg = lane & 3;
#pragma unroll
    for (int mi = 0; mi < 2; mi++) {
        const int r0 = m0 + wm + mi * 16 + g;
#pragma unroll
        for (int ni = 0; ni < 4; ni++) {
            const int c0 = n0 + wn + ni * 8 + 2 * tg;
            const float b0v = bias[((c0) & 3) * 1024 + (c0 >> 2)];
            const float b1v = bias[((c0 + 1) & 3) * 1024 + ((c0 + 1) >> 2)];
            *(float2*)&xp[(size_t)r0 * G4 + c0] =
                make_float2(acc[mi][ni][0] + b0v, acc[mi][ni][1] + b1v);
            *(float2*)&xp[(size_t)(r0 + 8) * G4 + c0] =
                make_float2(acc[mi][ni][2] + b0v, acc[mi][ni][3] + b1v);
        }
    }
}

// ---------------- persistent recurrence: all 256 steps, both directions ----------------
#define STEP_SMEM ((64 * SWH + 2 * 128 * ASTR) * 2)

__global__ __launch_bounds__(256, 1) void lstm_persistent()
{
    extern __shared__ __half dsm[];
    __half* WhS = dsm;                      // 64 x 1024 resident, stride SWH
    __half* As  = dsm + 64 * SWH;           // 2 stages of 128 x CW, stride ASTR
    float*  gbuf = (float*)As;              // 128 x 68 epilogue buffer (aliases As)

    const int tid = threadIdx.x, lane = tid & 31, warp = tid >> 5;
    const int wm = (warp & 3) * 32, wn = (warp >> 2) * 32;
    const int nt = blockIdx.x & 63, dir = blockIdx.x >> 6;
    const int n0 = nt * 64;

    const uint32_t asB = cvs(As);
    const uint32_t whB = cvs(WhS);

    // load resident Wh tile (64 rows x 1024 halfs)
    {
        const __half* Bg = g_whp[dir] + (size_t)n0 * HH;
#pragma unroll
        for (int i = 0; i < 32; i++) {
            int u = tid + i * 256, r = u >> 7, c8 = (u & 127) * 8;
            *(uint4*)(WhS + r * SWH + c8) = *(const uint4*)(Bg + (size_t)r * HH + c8);
        }
    }
    __syncthreads();

    float Creg[8], Mreg[8];
#pragma unroll
    for (int i = 0; i < 8; i++) { Creg[i] = 0.0f; Mreg[i] = -3.0e38f; }

    const int jj = tid & 15;                 // epilogue unit mapping (fixed per thread)

#pragma unroll 1
    for (int t = 0; t < TT; t++) {
        const int par = t & 1;
        const __half* Hsrc = g_Hst[par][dir];

        auto loadA = [&](int s, int kc) {
#pragma unroll
            for (int i = 0; i < 8; i++) {
                int u = tid + i * 256, r = u >> 4, c8 = (u & 15) * 8;
                cp16(asB + (uint32_t)((s * 128 * ASTR + r * ASTR + c8) << 1),
                     Hsrc + (size_t)r * HH + kc + c8);
            }
        };

        float acc[2][4][4];
#pragma unroll
        for (int a = 0; a < 2; a++)
#pragma unroll
            for (int b = 0; b < 4; b++)
#pragma unroll
                for (int c = 0; c < 4; c++) acc[a][b][c] = 0.0f;

        loadA(0, 0); cp_commit();
        const int NC = HH / CW;   // 8
#pragma unroll 1
        for (int c = 0; c < NC; c++) {
            if (c + 1 < NC) {
                loadA((c + 1) & 1, (c + 1) * CW);
                cp_commit();
                cp_wait<1>();
            } else {
                cp_wait<0>();
            }
            __syncthreads();
            mma_chunk<SWH>(asB + (uint32_t)(((c & 1) * 128 * ASTR) << 1),
                           whB + (uint32_t)((c * CW) << 1),
                           acc, lane, wm, wn);
            __syncthreads();
        }

        // stage accumulators to smem for gate-grouped access
        {
            const int g = lane >> 2, tg = lane & 3;
#pragma unroll
            for (int mi = 0; mi < 2; mi++) {
                const int r0 = wm + mi * 16 + g;
#pragma unroll
                for (int ni = 0; ni < 4; ni++) {
                    const int c0 = wn + ni * 8 + 2 * tg;
                    *(float2*)&gbuf[r0 * 68 + c0] =
                        make_float2(acc[mi][ni][0], acc[mi][ni][1]);
                    *(float2*)&gbuf[(r0 + 8) * 68 + c0] =
                        make_float2(acc[mi][ni][2], acc[mi][ni][3]);
                }
            }
        }
        __syncthreads();

        // fused LSTM cell epilogue
        const int xbase = (dir == 0) ? t : (TT - 1 - t);
        __half* Hdst = g_Hst[par ^ 1][dir];
#pragma unroll
        for (int i = 0; i < 8; i++) {
            const int it = tid + 256 * i;
            const int b  = it >> 4;
            float4 gv = *(float4*)&gbuf[b * 68 + 4 * jj];
            float4 xv = *(const float4*)&g_xp[dir][((size_t)xbase * BB + b) * G4 + n0 + 4 * jj];
            const float pi = gv.x + xv.x, pf = gv.y + xv.y;
            const float po = gv.z + xv.z, pc = gv.w + xv.w;
            float iv, fv, ov;
            if (dir == 0) { iv = sig_a(pi); fv = sig_a(pf); ov = sig_a(po); }
            else { iv = sig_a(sig_a(pi)); fv = sig_a(sig_a(pf)); ov = sig_a(sig_a(po)); }
            const float cv = tanh_a(pc);
            const float Cn = fv * Creg[i] + iv * cv;
            Creg[i] = Cn;
            const float Hn = ov * tanh_a(Cn);
            Hdst[b * HH + nt * 16 + jj] = __float2half(Hn);
            Mreg[i] = fmaxf(Mreg[i], Hn);
        }

        grid_sync();
    }

    // write max-pool result
#pragma unroll
    for (int i = 0; i < 8; i++) {
        const int it = tid + 256 * i;
        const int b  = it >> 4;
        g_maxH[dir][b * HH + nt * 16 + jj] = Mreg[i];
    }
}

// ---------------- classifier ----------------
__global__ __launch_bounds__(256) void fc1_kernel(const float* __restrict__ W1,
                                                  const float* __restrict__ b1)
{
    __shared__ float p[4][2048];
    const int b0 = blockIdx.x * 4;
    for (int i = threadIdx.x; i < 4 * 2048; i += 256) {
        const int r = i >> 11, c = i & 2047;
        float v = (c < 1024) ? g_maxH[0][(b0 + r) * HH + c]
                             : g_maxH[1][(b0 + r) * HH + (c - 1024)];
        p[r][c] = fmaxf(v, 0.0f);
    }
    __syncthreads();
    for (int j = threadIdx.x; j < 512; j += 256) {
        float a0 = b1[j], a1 = b1[j], a2 = b1[j], a3 = b1[j];
        for (int k = 0; k < 2048; k++) {
            const float w = W1[(size_t)k * 512 + j];
            a0 += p[0][k] * w; a1 += p[1][k] * w;
            a2 += p[2][k] * w; a3 += p[3][k] * w;
        }
        g_h1[(b0 + 0) * 512 + j] = a0;
        g_h1[(b0 + 1) * 512 + j] = a1;
        g_h1[(b0 + 2) * 512 + j] = a2;
        g_h1[(b0 + 3) * 512 + j] = a3;
    }
}

__global__ void fc2_kernel(const float* __restrict__ W2, const float* __restrict__ b2,
                           float* __restrict__ out)
{
    const int o = blockIdx.x * 256 + threadIdx.x;
    if (o < BB * 5) {
        const int b = o / 5, l = o % 5;
        float acc = b2[l];
        for (int k = 0; k < 512; k++)
            acc += g_h1[b * 512 + k] * W2[k * 5 + l];
        out[o] = acc;
    }
}

// ---------------- launch ----------------
extern "C" void kernel_launch(void* const* d_in, const int* in_sizes, int n_in,
                              void* d_out, int out_size)
{
    const int*   inputs    = (const int*)  d_in[0];
    const float* emb_table = (const float*)d_in[1];
    const float* Wxf       = (const float*)d_in[2];
    const float* Whf       = (const float*)d_in[3];
    const float* bhf       = (const float*)d_in[4];
    const float* Wxb       = (const float*)d_in[5];
    const float* Whb       = (const float*)d_in[6];
    const float* bhb       = (const float*)d_in[7];
    const float* W1        = (const float*)d_in[8];
    const float* b1        = (const float*)d_in[9];
    const float* W2        = (const float*)d_in[10];
    const float* b2        = (const float*)d_in[11];
    float* out = (float*)d_out;

    cudaFuncSetAttribute(proj_kernel, cudaFuncAttributeMaxDynamicSharedMemorySize, PROJ_SMEM);
    cudaFuncSetAttribute(lstm_persistent, cudaFuncAttributeMaxDynamicSharedMemorySize, STEP_SMEM);

    init_kernel<<<dim3(512, 2), 256>>>();
    prep_w2<<<dim3(EE / 32, 128), 256>>>(Wxf, 0, EE);
    prep_w2<<<dim3(EE / 32, 128), 256>>>(Wxb, 1, EE);
    prep_w2<<<dim3(HH / 32, 128), 256>>>(Whf, 2, HH);
    prep_w2<<<dim3(HH / 32, 128), 256>>>(Whb, 3, HH);
    gather_emb<<<TT * BB, 128>>>(inputs, emb_table);
    proj_kernel<<<dim3(64, 256, 2), 256, PROJ_SMEM>>>(bhf, bhb);
    lstm_persistent<<<NCTAS, 256, STEP_SMEM>>>();
    fc1_kernel<<<32, 256>>>(W1, b1);
    fc2_kernel<<<3, 256>>>(W2, b2, out);
}

// round 7
// speedup vs baseline: 2.4171x; 1.2635x over previous
#include <cuda_runtime.h>
#include <cuda_fp16.h>
#include <cstdint>

#define TT 256
#define BB 128
#define EE 512
#define HH 1024
#define G4 4096
#define NCTAS 128
#define CW 64                          // K chunk width (halfs)
#define NCH 24                         // 8 emb-chunks + 16 H-chunks (K = 512 + 1024)
#define WB_BYTES (64 * 1536 * 2)       // resident B tile [Wx|Wh], blocked SW128 atoms
#define STAGE_BYTES (128 * CW * 2)     // one A stage (128 rows x 64 halfs, swizzled)
#define SMEM_TOTAL (1024 + WB_BYTES + 2 * STAGE_BYTES)   // 230400 <= 232448

// ---------------- static device scratch ----------------
__device__ __half g_emb[(size_t)TT * BB * EE];
__device__ __half g_wxp[2][(size_t)G4 * EE];
__device__ __half g_whp[2][(size_t)G4 * HH];
__device__ __half g_Hst[2][2][BB * HH];
__device__ float  g_maxH[2][BB * HH];
__device__ float  g_h1[BB * 512];
__device__ unsigned g_cnt, g_gen;

// ---------------- primitives ----------------
__device__ __forceinline__ uint32_t cvs(const void* p) {
    return (uint32_t)__cvta_generic_to_shared(p);
}
__device__ __forceinline__ void cp16(uint32_t d, const void* s) {
    asm volatile("cp.async.cg.shared.global [%0], [%1], 16;" :: "r"(d), "l"(s));
}
__device__ __forceinline__ void cp_commit() { asm volatile("cp.async.commit_group;"); }
template <int N> __device__ __forceinline__ void cp_wait() {
    asm volatile("cp.async.wait_group %0;" :: "n"(N));
}
__device__ __forceinline__ void mma16816(float* c, const uint32_t a[4],
                                         uint32_t b0, uint32_t b1)
{
    asm volatile(
        "mma.sync.aligned.m16n8k16.row.col.f32.f16.f16.f32 "
        "{%0,%1,%2,%3},{%4,%5,%6,%7},{%8,%9},{%0,%1,%2,%3};\n"
        : "+f"(c[0]), "+f"(c[1]), "+f"(c[2]), "+f"(c[3])
        : "r"(a[0]), "r"(a[1]), "r"(a[2]), "r"(a[3]), "r"(b0), "r"(b1));
}
__device__ __forceinline__ void ldsm4(uint32_t& r0, uint32_t& r1, uint32_t& r2,
                                      uint32_t& r3, uint32_t a)
{
    asm volatile("ldmatrix.sync.aligned.m8n8.x4.shared.b16 {%0,%1,%2,%3},[%4];"
                 : "=r"(r0), "=r"(r1), "=r"(r2), "=r"(r3) : "r"(a));
}
__device__ __forceinline__ float tanh_a(float x) {
    float y; asm("tanh.approx.f32 %0, %1;" : "=f"(y) : "f"(x)); return y;
}
__device__ __forceinline__ float sig_a(float x) { return 0.5f * tanh_a(0.5f * x) + 0.5f; }

__device__ __forceinline__ uint32_t swz(uint32_t off) {
    return off ^ ((off >> 3) & 0x70);
}

__device__ __forceinline__ void grid_sync()
{
    __syncthreads();
    if (threadIdx.x == 0) {
        __threadfence();
        unsigned gen = atomicAdd(&g_gen, 0u);
        if (atomicAdd(&g_cnt, 1u) == NCTAS - 1u) {
            atomicExch(&g_cnt, 0u);
            __threadfence();
            atomicAdd(&g_gen, 1u);
        } else {
            while (atomicAdd(&g_gen, 0u) == gen) { }
        }
        __threadfence();
    }
    __syncthreads();
}

// ---------------- init ----------------
__global__ void init_kernel()
{
    const int i = blockIdx.x * 256 + threadIdx.x;
    const int d = blockIdx.y;
    if (i < BB * HH) g_Hst[0][d][i] = __float2half(0.0f);
    if (blockIdx.x == 0 && blockIdx.y == 0 && threadIdx.x == 0) { g_cnt = 0u; g_gen = 0u; }
}

// ---------------- weight prep: tiled transpose + fp16 + gate interleave ----------------
__global__ void prep_w2(const float* __restrict__ src, int which, int K)
{
    __half* dst = (which == 0) ? g_wxp[0] : (which == 1) ? g_wxp[1]
                : (which == 2) ? g_whp[0] : g_whp[1];
    __shared__ float tile[32][33];
    const int kt = blockIdx.x * 32;
    const int ct = blockIdx.y * 32;
    const int tx = threadIdx.x & 31, ty = threadIdx.x >> 5;
#pragma unroll
    for (int r = 0; r < 32; r += 8)
        tile[ty + r][tx] = src[(size_t)(kt + ty + r) * G4 + ct + tx];
    __syncthreads();
#pragma unroll
    for (int r = 0; r < 32; r += 8) {
        const int c  = ct + ty + r;
        const int np = ((c & 1023) << 2) | (c >> 10);
        dst[(size_t)np * K + kt + tx] = __float2half(tile[tx][ty + r]);
    }
}

// ---------------- embedding gather ----------------
__global__ void gather_emb(const int* __restrict__ inputs, const float* __restrict__ table)
{
    const int r = blockIdx.x;                 // t*B + b
    const int t = r >> 7, b = r & 127;
    const int idx = inputs[b * TT + t];
    const float* src = table + (size_t)idx * EE;
    __half* dst = g_emb + (size_t)r * EE;
    const int e = threadIdx.x * 4;
    float4 v = *(const float4*)(src + e);
    dst[e + 0] = __float2half(v.x);
    dst[e + 1] = __float2half(v.y);
    dst[e + 2] = __float2half(v.z);
    dst[e + 3] = __float2half(v.w);
}

// ---------------- fused persistent recurrence (mma.sync, proj folded into K) ----------------
// CTA = (nt, dir): owns 64 interleaved gate cols (16 hidden units). B resident = [Wx|Wh].
// Per step: A = [emb_t | H_prev] streamed in 24 K=64 chunks, D(128x64) in register acc.
__global__ __launch_bounds__(256, 1)
void lstm_fused(const float* __restrict__ bias_f, const float* __restrict__ bias_b)
{
    extern __shared__ char dsm[];
    const uint32_t sbRaw = cvs(dsm);
    const uint32_t wb  = (sbRaw + 1023u) & ~1023u;       // resident B (1024-aligned)
    const uint32_t st0 = wb + WB_BYTES;                  // A stage 0
    const uint32_t st1 = st0 + STAGE_BYTES;              // A stage 1

    const int tid = threadIdx.x, lane = tid & 31, wid = tid >> 5;
    const int nt = blockIdx.x & 63, dir = blockIdx.x >> 6;
    const int n0 = nt * 64;

    const int wm = (wid & 3) * 32, wn = (wid >> 2) * 32;
    const int g  = lane >> 2, tg = lane & 3;
    const int odd = lane & 1;

    // ---- load resident B = [Wx | Wh], blocked SW128 atoms (8 rows x 64 halfs) ----
    {
        const __half* wh = g_whp[dir];
        const __half* wx = g_wxp[dir];
        for (int idx = tid; idx < 64 * 192; idx += 256) {
            const int row = idx / 192;
            const int k8  = (idx % 192) * 8;             // K' in halfs (0..1528)
            uint32_t off = (uint32_t)((((row >> 3) + (k8 >> 6) * 8) << 10)
                         + ((row & 7) << 7) + ((k8 & 63) << 1));
            uint32_t d = wb + swz(off);
            uint4 v;
            if (k8 < 512) v = *(const uint4*)(wx + (size_t)(n0 + row) * EE + k8);
            else          v = *(const uint4*)(wh + (size_t)(n0 + row) * HH + (k8 - 512));
            asm volatile("st.shared.v4.b32 [%0], {%1,%2,%3,%4};"
                         :: "r"(d), "r"(v.x), "r"(v.y), "r"(v.z), "r"(v.w) : "memory");
        }
    }

    // ---- per-thread bias registers: 4 units (one per ni), 4 gates each ----
    float br[4][4];
    int   jg[4];                                         // global unit index per ni
    {
        const float* bias = dir ? bias_b : bias_f;
#pragma unroll
        for (int ni = 0; ni < 4; ni++) {
            jg[ni] = nt * 16 + (wn >> 2) + ni * 2 + (tg >> 1);
#pragma unroll
            for (int gt = 0; gt < 4; gt++)
                br[ni][gt] = bias[gt * 1024 + jg[ni]];
        }
    }

    float C[8], Mx[8];
#pragma unroll
    for (int q = 0; q < 8; q++) { C[q] = 0.0f; Mx[q] = -3.0e38f; }

    __syncthreads();

    // ldmatrix address components
    const int a_r  = lane & 15, a_kh = (lane >> 4) << 3;
    const int b_r  = lane & 7;
    const int sel  = lane >> 3;
    const int b_ni = (sel >> 1) << 3, b_kh = (sel & 1) << 3;

    // prologue: emb chunk 0 of t=0
    {
        const __half* Esrc = g_emb + (size_t)(dir ? (TT - 1) : 0) * BB * EE;
#pragma unroll
        for (int i = 0; i < 4; i++) {
            const int u = tid + (i << 8);
            const int row = u >> 3, k8 = (u & 7) << 3;
            uint32_t off = (uint32_t)(((row >> 3) << 10) | ((row & 7) << 7) | (k8 << 1));
            cp16(st0 + swz(off), Esrc + (size_t)row * EE + k8);
        }
        cp_commit();
    }

#pragma unroll 1
    for (int t = 0; t < TT; t++) {
        const int par = t & 1;
        const __half* Hsrc = g_Hst[par][dir];
        const __half* Esrc  = g_emb + (size_t)(dir ? (TT - 1 - t) : t) * BB * EE;
        const __half* EsrcN = g_emb + (size_t)(dir ? (TT - 2 - t) : (t + 1)) * BB * EE;

        auto stage = [&](int c, uint32_t dstB, const __half* Eptr) {
            const __half* src; int rstr;
            if (c < 8) { src = Eptr + c * 64; rstr = EE; }
            else       { src = Hsrc + (c - 8) * 64; rstr = HH; }
#pragma unroll
            for (int i = 0; i < 4; i++) {
                const int u = tid + (i << 8);
                const int row = u >> 3, k8 = (u & 7) << 3;
                uint32_t off = (uint32_t)(((row >> 3) << 10) | ((row & 7) << 7) | (k8 << 1));
                cp16(dstB + swz(off), src + (size_t)row * rstr + k8);
            }
            cp_commit();
        };

        float acc[2][4][4];
#pragma unroll
        for (int a = 0; a < 2; a++)
#pragma unroll
            for (int b = 0; b < 4; b++)
#pragma unroll
                for (int c2 = 0; c2 < 4; c2++) acc[a][b][c2] = 0.0f;

#pragma unroll 1
        for (int c = 0; c < NCH; c++) {
            __syncthreads();
            if (c + 1 < NCH) {
                stage(c + 1, (c & 1) ? st0 : st1, Esrc);
                cp_wait<1>();
            } else if (t + 1 < TT) {
                // prefetch emb chunk 0 of next step into st0 (overlaps epilogue+barrier)
                stage(0, st0, EsrcN);
                cp_wait<1>();
            } else {
                cp_wait<0>();
            }
            __syncthreads();

            const uint32_t aB = (c & 1) ? st1 : st0;
            const uint32_t bBase = wb + (uint32_t)c * 8192u;
#pragma unroll
            for (int ks = 0; ks < CW; ks += 16) {
                uint32_t a[2][4], b[4][2];
#pragma unroll
                for (int mi = 0; mi < 2; mi++) {
                    const int row = wm + mi * 16 + a_r;
                    const int kh  = ks + a_kh;
                    uint32_t off = (uint32_t)(((row >> 3) << 10) | ((row & 7) << 7) | (kh << 1));
                    ldsm4(a[mi][0], a[mi][1], a[mi][2], a[mi][3], aB + swz(off));
                }
#pragma unroll
                for (int p = 0; p < 2; p++) {
                    const int row = wn + p * 16 + b_ni + b_r;
                    const int kh  = ks + b_kh;
                    uint32_t off = (uint32_t)(((row >> 3) << 10) | ((row & 7) << 7) | (kh << 1));
                    ldsm4(b[2 * p][0], b[2 * p][1], b[2 * p + 1][0], b[2 * p + 1][1],
                          bBase + swz(off));
                }
#pragma unroll
                for (int mi = 0; mi < 2; mi++)
#pragma unroll
                    for (int ni = 0; ni < 4; ni++)
                        mma16816(acc[mi][ni], a[mi], b[ni][0], b[ni][1]);
            }
        }

        // ---- epilogue: shfl gate exchange + LSTM cell, state in regs ----
        __half* Hdst = g_Hst[par ^ 1][dir];
#pragma unroll
        for (int mi = 0; mi < 2; mi++) {
#pragma unroll
            for (int ni = 0; ni < 4; ni++) {
                const float v0 = acc[mi][ni][0], v1 = acc[mi][ni][1];
                const float v2 = acc[mi][ni][2], v3 = acc[mi][ni][3];
                const float rY = __shfl_xor_sync(0xffffffffu, odd ? v0 : v2, 1);
                const float rZ = __shfl_xor_sync(0xffffffffu, odd ? v1 : v3, 1);
                float pi, pf, po, pc;
                if (!odd) { pi = v0; pf = v1; po = rY; pc = rZ; }
                else      { pi = rY; pf = rZ; po = v2; pc = v3; }
                pi += br[ni][0]; pf += br[ni][1]; po += br[ni][2]; pc += br[ni][3];
                float iv, fv, ov;
                if (dir == 0) { iv = sig_a(pi); fv = sig_a(pf); ov = sig_a(po); }
                else { iv = sig_a(sig_a(pi)); fv = sig_a(sig_a(pf)); ov = sig_a(sig_a(po)); }
                const float cv = tanh_a(pc);
                const int q = mi * 4 + ni;
                const float Cn = fv * C[q] + iv * cv;
                C[q] = Cn;
                const float Hn = ov * tanh_a(Cn);
                Mx[q] = fmaxf(Mx[q], Hn);
                const int row = wm + mi * 16 + g + (odd << 3);
                Hdst[row * HH + jg[ni]] = __float2half(Hn);
            }
        }

        grid_sync();
    }

    // ---- write max-pool result ----
#pragma unroll
    for (int mi = 0; mi < 2; mi++) {
        const int row = wm + mi * 16 + g + (odd << 3);
#pragma unroll
        for (int ni = 0; ni < 4; ni++)
            g_maxH[dir][row * HH + jg[ni]] = Mx[mi * 4 + ni];
    }
}

// ---------------- classifier ----------------
__global__ __launch_bounds__(256) void fc1_kernel(const float* __restrict__ W1,
                                                  const float* __restrict__ b1)
{
    __shared__ float p[4][2048];
    const int b0 = blockIdx.x * 4;
    for (int i = threadIdx.x; i < 4 * 2048; i += 256) {
        const int r = i >> 11, c = i & 2047;
        float v = (c < 1024) ? g_maxH[0][(b0 + r) * HH + c]
                             : g_maxH[1][(b0 + r) * HH + (c - 1024)];
        p[r][c] = fmaxf(v, 0.0f);
    }
    __syncthreads();
    for (int j = threadIdx.x; j < 512; j += 256) {
        float a0 = b1[j], a1 = b1[j], a2 = b1[j], a3 = b1[j];
        for (int k = 0; k < 2048; k++) {
            const float w = W1[(size_t)k * 512 + j];
            a0 += p[0][k] * w; a1 += p[1][k] * w;
            a2 += p[2][k] * w; a3 += p[3][k] * w;
        }
        g_h1[(b0 + 0) * 512 + j] = a0;
        g_h1[(b0 + 1) * 512 + j] = a1;
        g_h1[(b0 + 2) * 512 + j] = a2;
        g_h1[(b0 + 3) * 512 + j] = a3;
    }
}

__global__ void fc2_kernel(const float* __restrict__ W2, const float* __restrict__ b2,
                           float* __restrict__ out)
{
    const int o = blockIdx.x * 256 + threadIdx.x;
    if (o < BB * 5) {
        const int b = o / 5, l = o % 5;
        float acc = b2[l];
        for (int k = 0; k < 512; k++)
            acc += g_h1[b * 512 + k] * W2[k * 5 + l];
        out[o] = acc;
    }
}

// ---------------- launch ----------------
extern "C" void kernel_launch(void* const* d_in, const int* in_sizes, int n_in,
                              void* d_out, int out_size)
{
    const int*   inputs    = (const int*)  d_in[0];
    const float* emb_table = (const float*)d_in[1];
    const float* Wxf       = (const float*)d_in[2];
    const float* Whf       = (const float*)d_in[3];
    const float* bhf       = (const float*)d_in[4];
    const float* Wxb       = (const float*)d_in[5];
    const float* Whb       = (const float*)d_in[6];
    const float* bhb       = (const float*)d_in[7];
    const float* W1        = (const float*)d_in[8];
    const float* b1        = (const float*)d_in[9];
    const float* W2        = (const float*)d_in[10];
    const float* b2        = (const float*)d_in[11];
    float* out = (float*)d_out;

    cudaFuncSetAttribute(lstm_fused, cudaFuncAttributeMaxDynamicSharedMemorySize, SMEM_TOTAL);

    init_kernel<<<dim3(512, 2), 256>>>();
    prep_w2<<<dim3(EE / 32, 128), 256>>>(Wxf, 0, EE);
    prep_w2<<<dim3(EE / 32, 128), 256>>>(Wxb, 1, EE);
    prep_w2<<<dim3(HH / 32, 128), 256>>>(Whf, 2, HH);
    prep_w2<<<dim3(HH / 32, 128), 256>>>(Whb, 3, HH);
    gather_emb<<<TT * BB, 128>>>(inputs, emb_table);
    lstm_fused<<<NCTAS, 256, SMEM_TOTAL>>>(bhf, bhb);
    fc1_kernel<<<32, 256>>>(W1, b1);
    fc2_kernel<<<3, 256>>>(W2, b2, out);
}